// round 13
// baseline (speedup 1.0000x reference)
#include <cuda_runtime.h>
#include <cuda_bf16.h>
#include <math.h>

#define NN 100000
#define NE 3200000
#define NG 512
#define F 20          // hidden width
#define ZP 32         // padded z row (floats) = 128B
#define CAP 96        // fixed slots per node (max degree ~65 for Poisson(32))

// ---------------- scratch (device globals; no allocation allowed) ------------
__device__ int                g_pos[NN];           // scatter cursor (starts 0, reset each call)
__device__ int                g_cnt[NN];           // padded degree (multiple of 3)
__device__ unsigned long long g_epack[(long)NN * CAP]; // bucket payload: (ew_bits<<32)|src
__device__ float              g_z[NN * ZP];        // rel-transformed, 128B-aligned rows
__device__ float              g_r[NN * F];         // root term + bias
__device__ float              g_h[NN * F];         // current node features

// ---------------- scatter: 8 edges per thread (guarded), bucketed by dst ------
__global__ void __launch_bounds__(256) scatter_kernel(const int* __restrict__ src,
                                                      const int* __restrict__ dst,
                                                      const float* __restrict__ ew) {
    int t = blockIdx.x * blockDim.x + threadIdx.x;
    if (t * 8 >= NE) return;                        // exact bound: no phantom edges
    int4   sv0 = *reinterpret_cast<const int4*>(src + t * 8);
    int4   sv1 = *reinterpret_cast<const int4*>(src + t * 8 + 4);
    int4   dv0 = *reinterpret_cast<const int4*>(dst + t * 8);
    int4   dv1 = *reinterpret_cast<const int4*>(dst + t * 8 + 4);
    float4 wv0 = *reinterpret_cast<const float4*>(ew + t * 8);
    float4 wv1 = *reinterpret_cast<const float4*>(ew + t * 8 + 4);

    int c0 = atomicAdd(&g_pos[dv0.x], 1);
    int c1 = atomicAdd(&g_pos[dv0.y], 1);
    int c2 = atomicAdd(&g_pos[dv0.z], 1);
    int c3 = atomicAdd(&g_pos[dv0.w], 1);
    int c4 = atomicAdd(&g_pos[dv1.x], 1);
    int c5 = atomicAdd(&g_pos[dv1.y], 1);
    int c6 = atomicAdd(&g_pos[dv1.z], 1);
    int c7 = atomicAdd(&g_pos[dv1.w], 1);

    if (c0 < CAP) g_epack[(long)dv0.x * CAP + c0] =
        ((unsigned long long)__float_as_uint(wv0.x) << 32) | (unsigned)sv0.x;
    if (c1 < CAP) g_epack[(long)dv0.y * CAP + c1] =
        ((unsigned long long)__float_as_uint(wv0.y) << 32) | (unsigned)sv0.y;
    if (c2 < CAP) g_epack[(long)dv0.z * CAP + c2] =
        ((unsigned long long)__float_as_uint(wv0.z) << 32) | (unsigned)sv0.z;
    if (c3 < CAP) g_epack[(long)dv0.w * CAP + c3] =
        ((unsigned long long)__float_as_uint(wv0.w) << 32) | (unsigned)sv0.w;
    if (c4 < CAP) g_epack[(long)dv1.x * CAP + c4] =
        ((unsigned long long)__float_as_uint(wv1.x) << 32) | (unsigned)sv1.x;
    if (c5 < CAP) g_epack[(long)dv1.y * CAP + c5] =
        ((unsigned long long)__float_as_uint(wv1.y) << 32) | (unsigned)sv1.y;
    if (c6 < CAP) g_epack[(long)dv1.z * CAP + c6] =
        ((unsigned long long)__float_as_uint(wv1.z) << 32) | (unsigned)sv1.z;
    if (c7 < CAP) g_epack[(long)dv1.w * CAP + c7] =
        ((unsigned long long)__float_as_uint(wv1.w) << 32) | (unsigned)sv1.w;
}

// ---------------- transform v2: thread per (node, output-quad) ----------------
// p = t%10: p<5 -> z-quad p (f@Wrel^T), p>=5 -> r-quad p-5 (f@Wroot^T + b).
// FIN==10 additionally runs padzero (pad counts to multiple of 3) on p==0 threads.
template <int FIN>
__global__ void __launch_bounds__(256) transform_kernel(const float* __restrict__ xext,
                                                        const float* __restrict__ Wrel,
                                                        const float* __restrict__ brel,
                                                        const float* __restrict__ Wroot,
                                                        int insel) {
    __shared__ float sWrel[F * FIN];
    __shared__ float sWroot[F * FIN];
    __shared__ float sb[F];
    for (int i = threadIdx.x; i < F * FIN; i += blockDim.x) {
        sWrel[i]  = Wrel[i];
        sWroot[i] = Wroot[i];
    }
    if (threadIdx.x < F) sb[threadIdx.x] = brel[threadIdx.x];
    __syncthreads();

    int t = blockIdx.x * blockDim.x + threadIdx.x;
    int n = t / 10;
    int p = t - n * 10;
    if (n >= NN) return;

    if (FIN == 10 && p == 0) {   // layer 1: finalize CSR buckets
        int cnt = g_pos[n];
        if (cnt > CAP) cnt = CAP;
        int cntp = ((cnt + 2) / 3) * 3;             // multiple of 3, <= 96
        unsigned long long* pp = g_epack + (long)n * CAP;
        for (int j = cnt; j < cntp; j++) pp[j] = 0ull;
        g_cnt[n] = cntp;
        g_pos[n] = 0;
    }

    const float* fin = (insel < 0) ? xext : g_h;
    float f[FIN];
    if (FIN == 20) {
        const float4* fp = reinterpret_cast<const float4*>(fin + (long)n * FIN);
        #pragma unroll
        for (int q = 0; q < 5; q++) {
            float4 v = __ldg(fp + q);
            f[q * 4 + 0] = v.x; f[q * 4 + 1] = v.y; f[q * 4 + 2] = v.z; f[q * 4 + 3] = v.w;
        }
    } else {
        const float2* fp = reinterpret_cast<const float2*>(fin + (long)n * FIN);
        #pragma unroll
        for (int q = 0; q < 5; q++) {
            float2 v = __ldg(fp + q);
            f[q * 2 + 0] = v.x; f[q * 2 + 1] = v.y;
        }
    }

    bool is_z = p < 5;
    int  quad = is_z ? p : p - 5;
    const float* W = is_z ? sWrel : sWroot;

    float4 o;
    float* op = &o.x;
    #pragma unroll
    for (int i = 0; i < 4; i++) {
        int j = quad * 4 + i;
        float a = is_z ? 0.0f : sb[j];
        if (FIN == 20) {
            const float4* wr = reinterpret_cast<const float4*>(W + j * FIN);
            #pragma unroll
            for (int k = 0; k < 5; k++) {
                float4 wv = wr[k];
                a += f[k * 4 + 0] * wv.x + f[k * 4 + 1] * wv.y
                   + f[k * 4 + 2] * wv.z + f[k * 4 + 3] * wv.w;
            }
        } else {
            const float2* wr = reinterpret_cast<const float2*>(W + j * FIN);
            #pragma unroll
            for (int k = 0; k < 5; k++) {
                float2 wv = wr[k];
                a += f[k * 2 + 0] * wv.x + f[k * 2 + 1] * wv.y;
            }
        }
        op[i] = a;
    }

    if (is_z)
        *reinterpret_cast<float4*>(g_z + (long)n * ZP + quad * 4) = o;
    else
        *reinterpret_cast<float4*>(g_r + (long)n * F + quad * 4) = o;
}

// ---------------- gather: 2 nodes per warp, 15 lanes each (3 edges x 5 quads) -
// (round-11 version: pad-to-3, warp-uniform break in sub loop)
__global__ void __launch_bounds__(256) gather_kernel() {
    const unsigned FULL = 0xffffffffu;
    int gwarp = (blockIdx.x * blockDim.x + threadIdx.x) >> 5;   // 0..NN/2-1
    if (gwarp >= NN / 2) return;
    int lane   = threadIdx.x & 31;
    int half   = lane & 16;         // 0 or 16
    int local  = lane & 15;         // 0..15
    int e_slot = local / 5;         // 0..2 (3 for local 15, unused)
    int q      = local % 5;
    const bool use = local < 15;

    int  node = 2 * gwarp + (half >> 4);
    long s0   = (long)node * CAP;
    int  cntp = g_cnt[node];                          // multiple of 3
    int  cmax = max(cntp, __shfl_xor_sync(FULL, cntp, 16));

    float4 acc = make_float4(0.f, 0.f, 0.f, 0.f);

    for (int base = 0; base < cmax; base += 15) {
        unsigned lo = 0u, hi = 0u;
        int idx = base + local;
        if (use && idx < cntp) {
            unsigned long long pk = g_epack[s0 + idx];
            lo = (unsigned)pk;
            hi = (unsigned)(pk >> 32);
        }
        int rem = cmax - base;       // multiple of 3, > 0
        #pragma unroll
        for (int sub = 0; sub < 5; sub++) {
            if (sub * 3 >= rem) break;               // warp-uniform
            int   sl = half + sub * 3 + e_slot;      // payload lane for this slot
            int   s  = __shfl_sync(FULL, lo, sl);
            float w  = __uint_as_float(__shfl_sync(FULL, hi, sl));
            if (use) {
                float4 row = *reinterpret_cast<const float4*>(g_z + s * ZP + q * 4);
                acc.x += w * row.x;
                acc.y += w * row.y;
                acc.z += w * row.z;
                acc.w += w * row.w;
            }
        }
    }

    // reduce 3 edge-slots within each half: locals 0-4 <- (0-4)+(5-9)+(10-14)
    float4 a1, tot;
    a1.x = acc.x + __shfl_down_sync(FULL, acc.x, 5);
    a1.y = acc.y + __shfl_down_sync(FULL, acc.y, 5);
    a1.z = acc.z + __shfl_down_sync(FULL, acc.z, 5);
    a1.w = acc.w + __shfl_down_sync(FULL, acc.w, 5);
    tot.x = a1.x + __shfl_down_sync(FULL, acc.x, 10);
    tot.y = a1.y + __shfl_down_sync(FULL, acc.y, 10);
    tot.z = a1.z + __shfl_down_sync(FULL, acc.z, 10);
    tot.w = a1.w + __shfl_down_sync(FULL, acc.w, 10);

    // locals 0-4 hold quad q=local; add root term, normalize, relu, store
    float4 val = make_float4(0.f, 0.f, 0.f, 0.f);
    if (local < 5) {
        float4 rq = *reinterpret_cast<const float4*>(g_r + (long)node * F + local * 4);
        val.x = tot.x + rq.x;
        val.y = tot.y + rq.y;
        val.z = tot.z + rq.z;
        val.w = tot.w + rq.w;
    }
    float ss = val.x * val.x + val.y * val.y + val.z * val.z + val.w * val.w;
    float sstot = ss
        + __shfl_down_sync(FULL, ss, 1)
        + __shfl_down_sync(FULL, ss, 2)
        + __shfl_down_sync(FULL, ss, 3)
        + __shfl_down_sync(FULL, ss, 4);
    sstot = __shfl_sync(FULL, sstot, half);   // each half broadcasts its total
    float inv = 1.0f / fmaxf(sqrtf(sstot), 1e-12f);

    if (local < 5) {
        float4 o;
        o.x = fmaxf(val.x * inv, 0.0f);
        o.y = fmaxf(val.y * inv, 0.0f);
        o.z = fmaxf(val.z * inv, 0.0f);
        o.w = fmaxf(val.w * inv, 0.0f);
        *reinterpret_cast<float4*>(g_h + (long)node * F + local * 4) = o;
    }
}

// ---------------- pooling + final linear (batch sorted -> no atomics) --------
__device__ __forceinline__ int lower_bound_i(const int* __restrict__ a, int n, int key) {
    int lo = 0, hi = n;
    while (lo < hi) {
        int m = (lo + hi) >> 1;
        if (a[m] < key) lo = m + 1; else hi = m;
    }
    return lo;
}

__global__ void __launch_bounds__(256) pool_kernel(const int* __restrict__ batch,
                                                   const float* __restrict__ Wlin,
                                                   const float* __restrict__ blin,
                                                   float* __restrict__ out) {
    const float* emb = g_h;
    int g = blockIdx.x;

    __shared__ int s_lo, s_hi;
    if (threadIdx.x == 0) {
        s_lo = lower_bound_i(batch, NN, g);
        s_hi = lower_bound_i(batch, NN, g + 1);
    }
    __syncthreads();
    int lo = s_lo, hi = s_hi;

    float sm[F], mx[F];
    #pragma unroll
    for (int k = 0; k < F; k++) { sm[k] = 0.0f; mx[k] = 0.0f; }

    for (int i = lo + threadIdx.x; i < hi; i += blockDim.x) {
        const float* r = emb + (long)i * F;
        #pragma unroll
        for (int k = 0; k < F; k++) {
            float v = __ldg(r + k);
            sm[k] += v;
            mx[k] = fmaxf(mx[k], v);
        }
    }

    #pragma unroll
    for (int o = 16; o > 0; o >>= 1) {
        #pragma unroll
        for (int k = 0; k < F; k++) {
            sm[k] += __shfl_down_sync(0xffffffffu, sm[k], o);
            mx[k] = fmaxf(mx[k], __shfl_down_sync(0xffffffffu, mx[k], o));
        }
    }

    __shared__ float ssum[8][F];
    __shared__ float smax[8][F];
    int w = threadIdx.x >> 5, lane = threadIdx.x & 31;
    if (lane == 0) {
        #pragma unroll
        for (int k = 0; k < F; k++) { ssum[w][k] = sm[k]; smax[w][k] = mx[k]; }
    }
    __syncthreads();

    if (threadIdx.x == 0) {
        float fs[F], fm[F];
        #pragma unroll
        for (int k = 0; k < F; k++) { fs[k] = 0.0f; fm[k] = 0.0f; }
        for (int ww = 0; ww < 8; ww++)
            for (int k = 0; k < F; k++) {
                fs[k] += ssum[ww][k];
                fm[k] = fmaxf(fm[k], smax[ww][k]);
            }
        float cnt  = (float)(hi - lo);
        float invc = 1.0f / fmaxf(cnt, 1.0f);
        #pragma unroll
        for (int c = 0; c < 2; c++) {
            float v = blin[c];
            for (int k = 0; k < F; k++) v += fm[k] * Wlin[c * 40 + k];
            for (int k = 0; k < F; k++) v += fs[k] * invc * Wlin[c * 40 + 20 + k];
            out[g * 2 + c] = v;
        }
    }
}

// ---------------- launch ------------------------------------------------------
extern "C" void kernel_launch(void* const* d_in, const int* in_sizes, int n_in,
                              void* d_out, int out_size) {
    (void)in_sizes; (void)n_in; (void)out_size;

    const float* x      = (const float*)d_in[0];
    const int*   ei     = (const int*)  d_in[1];   // [2, NE]: row0=src, row1=dst
    const int*   batch  = (const int*)  d_in[2];
    const float* ew     = (const float*)d_in[3];
    const float* W1_rel = (const float*)d_in[4];
    const float* b1_rel = (const float*)d_in[5];
    const float* W1_root= (const float*)d_in[6];
    const float* W2_rel = (const float*)d_in[7];
    const float* b2_rel = (const float*)d_in[8];
    const float* W2_root= (const float*)d_in[9];
    const float* W3_rel = (const float*)d_in[10];
    const float* b3_rel = (const float*)d_in[11];
    const float* W3_root= (const float*)d_in[12];
    const float* W_lin  = (const float*)d_in[13];
    const float* b_lin  = (const float*)d_in[14];
    float* out = (float*)d_out;

    const int* src = ei;
    const int* dst = ei + NE;

    const int TB = 256;
    const int GB_T  = (NN * 10 + TB - 1) / TB;          // 3907 (transform v2)
    const int GB_E8 = (NE / 8 + TB - 1) / TB;           // 1563 (guarded in-kernel)
    const int GB_W  = ((NN / 2) * 32 + TB - 1) / TB;    // 6250

    scatter_kernel<<<GB_E8, TB>>>(src, dst, ew);                          // 0

    transform_kernel<10><<<GB_T, TB>>>(x, W1_rel, b1_rel, W1_root, -1);   // 1 (+padzero)
    gather_kernel<<<GB_W, TB>>>();                                         // 2
    transform_kernel<20><<<GB_T, TB>>>(x, W2_rel, b2_rel, W2_root, 0);    // 3
    gather_kernel<<<GB_W, TB>>>();                                         // 4
    transform_kernel<20><<<GB_T, TB>>>(x, W3_rel, b3_rel, W3_root, 0);    // 5
    gather_kernel<<<GB_W, TB>>>();                                         // 6

    pool_kernel<<<NG, 256>>>(batch, W_lin, b_lin, out);                    // 7
}

// round 14
// speedup vs baseline: 1.2046x; 1.2046x over previous
#include <cuda_runtime.h>
#include <cuda_bf16.h>
#include <math.h>

#define NN 100000
#define NE 3200000
#define NG 512
#define F 20          // hidden width
#define ZP 32         // padded z row (floats) = 128B
#define CAP 96        // fixed slots per node (max degree ~65 for Poisson(32))

// ---------------- scratch (device globals; no allocation allowed) ------------
__device__ int                g_pos[NN];           // scatter cursor (starts 0, reset each call)
__device__ int                g_cnt[NN];           // padded degree (multiple of 3)
__device__ unsigned long long g_epack[(long)NN * CAP]; // bucket payload: (ew_bits<<32)|src
__device__ float              g_z[NN * ZP];        // rel-transformed, 128B-aligned rows
__device__ float              g_r[NN * F];         // root term + bias
__device__ float              g_h[NN * F];         // current node features

// ---------------- scatter: 8 edges per thread (guarded), bucketed by dst ------
__global__ void __launch_bounds__(256) scatter_kernel(const int* __restrict__ src,
                                                      const int* __restrict__ dst,
                                                      const float* __restrict__ ew) {
    int t = blockIdx.x * blockDim.x + threadIdx.x;
    if (t * 8 >= NE) return;                        // exact bound: no phantom edges
    int4   sv0 = *reinterpret_cast<const int4*>(src + t * 8);
    int4   sv1 = *reinterpret_cast<const int4*>(src + t * 8 + 4);
    int4   dv0 = *reinterpret_cast<const int4*>(dst + t * 8);
    int4   dv1 = *reinterpret_cast<const int4*>(dst + t * 8 + 4);
    float4 wv0 = *reinterpret_cast<const float4*>(ew + t * 8);
    float4 wv1 = *reinterpret_cast<const float4*>(ew + t * 8 + 4);

    int c0 = atomicAdd(&g_pos[dv0.x], 1);
    int c1 = atomicAdd(&g_pos[dv0.y], 1);
    int c2 = atomicAdd(&g_pos[dv0.z], 1);
    int c3 = atomicAdd(&g_pos[dv0.w], 1);
    int c4 = atomicAdd(&g_pos[dv1.x], 1);
    int c5 = atomicAdd(&g_pos[dv1.y], 1);
    int c6 = atomicAdd(&g_pos[dv1.z], 1);
    int c7 = atomicAdd(&g_pos[dv1.w], 1);

    if (c0 < CAP) g_epack[(long)dv0.x * CAP + c0] =
        ((unsigned long long)__float_as_uint(wv0.x) << 32) | (unsigned)sv0.x;
    if (c1 < CAP) g_epack[(long)dv0.y * CAP + c1] =
        ((unsigned long long)__float_as_uint(wv0.y) << 32) | (unsigned)sv0.y;
    if (c2 < CAP) g_epack[(long)dv0.z * CAP + c2] =
        ((unsigned long long)__float_as_uint(wv0.z) << 32) | (unsigned)sv0.z;
    if (c3 < CAP) g_epack[(long)dv0.w * CAP + c3] =
        ((unsigned long long)__float_as_uint(wv0.w) << 32) | (unsigned)sv0.w;
    if (c4 < CAP) g_epack[(long)dv1.x * CAP + c4] =
        ((unsigned long long)__float_as_uint(wv1.x) << 32) | (unsigned)sv1.x;
    if (c5 < CAP) g_epack[(long)dv1.y * CAP + c5] =
        ((unsigned long long)__float_as_uint(wv1.y) << 32) | (unsigned)sv1.y;
    if (c6 < CAP) g_epack[(long)dv1.z * CAP + c6] =
        ((unsigned long long)__float_as_uint(wv1.z) << 32) | (unsigned)sv1.z;
    if (c7 < CAP) g_epack[(long)dv1.w * CAP + c7] =
        ((unsigned long long)__float_as_uint(wv1.w) << 32) | (unsigned)sv1.w;
}

// ---------------- transform v3: warp GEMM, lane j holds weight row j ----------
// Warp processes 16 nodes. Lane j<20: Wrel[j][:], Wroot[j][:] in registers.
// Per node: f loaded via uniform-address float4 __ldg (broadcast, 1 wavefront),
// 40 FMA, 2 coalesced stores. FIN==10 runs padzero on idle lane 20.
template <int FIN>
__global__ void __launch_bounds__(256) transform_kernel(const float* __restrict__ xext,
                                                        const float* __restrict__ Wrel,
                                                        const float* __restrict__ brel,
                                                        const float* __restrict__ Wroot,
                                                        int insel) {
    int gwarp = (blockIdx.x * blockDim.x + threadIdx.x) >> 5;
    int lane  = threadIdx.x & 31;
    int n0    = gwarp * 16;
    if (n0 >= NN) return;                // NN = 6250*16 exactly; full warps only

    float wr[FIN], wo[FIN];
    float bias = 0.0f;
    if (lane < F) {
        #pragma unroll
        for (int k = 0; k < FIN; k++) {
            wr[k] = __ldg(Wrel  + lane * FIN + k);
            wo[k] = __ldg(Wroot + lane * FIN + k);
        }
        bias = __ldg(brel + lane);
    }

    const float* fin = (insel < 0) ? xext : g_h;

    #pragma unroll 2
    for (int i = 0; i < 16; i++) {
        int n = n0 + i;

        if (FIN == 10 && lane == 20) {   // layer 1: finalize CSR bucket for n
            int cnt = g_pos[n];
            if (cnt > CAP) cnt = CAP;
            int cntp = ((cnt + 2) / 3) * 3;            // multiple of 3, <= 96
            unsigned long long* pp = g_epack + (long)n * CAP;
            for (int j = cnt; j < cntp; j++) pp[j] = 0ull;
            g_cnt[n] = cntp;
            g_pos[n] = 0;
        }

        float zacc = 0.0f, racc = bias;
        const float* fr = fin + (long)n * FIN;
        if (FIN == 20) {
            #pragma unroll
            for (int q = 0; q < 5; q++) {
                float4 fv = __ldg(reinterpret_cast<const float4*>(fr) + q);
                zacc += wr[q*4+0]*fv.x + wr[q*4+1]*fv.y + wr[q*4+2]*fv.z + wr[q*4+3]*fv.w;
                racc += wo[q*4+0]*fv.x + wo[q*4+1]*fv.y + wo[q*4+2]*fv.z + wo[q*4+3]*fv.w;
            }
        } else {
            #pragma unroll
            for (int q = 0; q < 5; q++) {
                float2 fv = __ldg(reinterpret_cast<const float2*>(fr) + q);
                zacc += wr[q*2+0]*fv.x + wr[q*2+1]*fv.y;
                racc += wo[q*2+0]*fv.x + wo[q*2+1]*fv.y;
            }
        }
        if (lane < F) {
            g_z[(long)n * ZP + lane] = zacc;   // 20 lanes, 80B contiguous
            g_r[(long)n * F  + lane] = racc;
        }
    }
}

// ---------------- gather: 2 nodes per warp, 15 lanes each (3 edges x 5 quads) -
// (round-11 version: pad-to-3, warp-uniform break in sub loop)
__global__ void __launch_bounds__(256) gather_kernel() {
    const unsigned FULL = 0xffffffffu;
    int gwarp = (blockIdx.x * blockDim.x + threadIdx.x) >> 5;   // 0..NN/2-1
    if (gwarp >= NN / 2) return;
    int lane   = threadIdx.x & 31;
    int half   = lane & 16;         // 0 or 16
    int local  = lane & 15;         // 0..15
    int e_slot = local / 5;         // 0..2 (3 for local 15, unused)
    int q      = local % 5;
    const bool use = local < 15;

    int  node = 2 * gwarp + (half >> 4);
    long s0   = (long)node * CAP;
    int  cntp = g_cnt[node];                          // multiple of 3
    int  cmax = max(cntp, __shfl_xor_sync(FULL, cntp, 16));

    float4 acc = make_float4(0.f, 0.f, 0.f, 0.f);

    for (int base = 0; base < cmax; base += 15) {
        unsigned lo = 0u, hi = 0u;
        int idx = base + local;
        if (use && idx < cntp) {
            unsigned long long pk = g_epack[s0 + idx];
            lo = (unsigned)pk;
            hi = (unsigned)(pk >> 32);
        }
        int rem = cmax - base;       // multiple of 3, > 0
        #pragma unroll
        for (int sub = 0; sub < 5; sub++) {
            if (sub * 3 >= rem) break;               // warp-uniform
            int   sl = half + sub * 3 + e_slot;      // payload lane for this slot
            int   s  = __shfl_sync(FULL, lo, sl);
            float w  = __uint_as_float(__shfl_sync(FULL, hi, sl));
            if (use) {
                float4 row = *reinterpret_cast<const float4*>(g_z + s * ZP + q * 4);
                acc.x += w * row.x;
                acc.y += w * row.y;
                acc.z += w * row.z;
                acc.w += w * row.w;
            }
        }
    }

    // reduce 3 edge-slots within each half: locals 0-4 <- (0-4)+(5-9)+(10-14)
    float4 a1, tot;
    a1.x = acc.x + __shfl_down_sync(FULL, acc.x, 5);
    a1.y = acc.y + __shfl_down_sync(FULL, acc.y, 5);
    a1.z = acc.z + __shfl_down_sync(FULL, acc.z, 5);
    a1.w = acc.w + __shfl_down_sync(FULL, acc.w, 5);
    tot.x = a1.x + __shfl_down_sync(FULL, acc.x, 10);
    tot.y = a1.y + __shfl_down_sync(FULL, acc.y, 10);
    tot.z = a1.z + __shfl_down_sync(FULL, acc.z, 10);
    tot.w = a1.w + __shfl_down_sync(FULL, acc.w, 10);

    // locals 0-4 hold quad q=local; add root term, normalize, relu, store
    float4 val = make_float4(0.f, 0.f, 0.f, 0.f);
    if (local < 5) {
        float4 rq = *reinterpret_cast<const float4*>(g_r + (long)node * F + local * 4);
        val.x = tot.x + rq.x;
        val.y = tot.y + rq.y;
        val.z = tot.z + rq.z;
        val.w = tot.w + rq.w;
    }
    float ss = val.x * val.x + val.y * val.y + val.z * val.z + val.w * val.w;
    float sstot = ss
        + __shfl_down_sync(FULL, ss, 1)
        + __shfl_down_sync(FULL, ss, 2)
        + __shfl_down_sync(FULL, ss, 3)
        + __shfl_down_sync(FULL, ss, 4);
    sstot = __shfl_sync(FULL, sstot, half);   // each half broadcasts its total
    float inv = 1.0f / fmaxf(sqrtf(sstot), 1e-12f);

    if (local < 5) {
        float4 o;
        o.x = fmaxf(val.x * inv, 0.0f);
        o.y = fmaxf(val.y * inv, 0.0f);
        o.z = fmaxf(val.z * inv, 0.0f);
        o.w = fmaxf(val.w * inv, 0.0f);
        *reinterpret_cast<float4*>(g_h + (long)node * F + local * 4) = o;
    }
}

// ---------------- pooling + final linear (batch sorted -> no atomics) --------
__device__ __forceinline__ int lower_bound_i(const int* __restrict__ a, int n, int key) {
    int lo = 0, hi = n;
    while (lo < hi) {
        int m = (lo + hi) >> 1;
        if (a[m] < key) lo = m + 1; else hi = m;
    }
    return lo;
}

__global__ void __launch_bounds__(256) pool_kernel(const int* __restrict__ batch,
                                                   const float* __restrict__ Wlin,
                                                   const float* __restrict__ blin,
                                                   float* __restrict__ out) {
    const float* emb = g_h;
    int g = blockIdx.x;

    __shared__ int s_lo, s_hi;
    if (threadIdx.x == 0) {
        s_lo = lower_bound_i(batch, NN, g);
        s_hi = lower_bound_i(batch, NN, g + 1);
    }
    __syncthreads();
    int lo = s_lo, hi = s_hi;

    float sm[F], mx[F];
    #pragma unroll
    for (int k = 0; k < F; k++) { sm[k] = 0.0f; mx[k] = 0.0f; }

    for (int i = lo + threadIdx.x; i < hi; i += blockDim.x) {
        const float* r = emb + (long)i * F;
        #pragma unroll
        for (int k = 0; k < F; k++) {
            float v = __ldg(r + k);
            sm[k] += v;
            mx[k] = fmaxf(mx[k], v);
        }
    }

    #pragma unroll
    for (int o = 16; o > 0; o >>= 1) {
        #pragma unroll
        for (int k = 0; k < F; k++) {
            sm[k] += __shfl_down_sync(0xffffffffu, sm[k], o);
            mx[k] = fmaxf(mx[k], __shfl_down_sync(0xffffffffu, mx[k], o));
        }
    }

    __shared__ float ssum[8][F];
    __shared__ float smax[8][F];
    int w = threadIdx.x >> 5, lane = threadIdx.x & 31;
    if (lane == 0) {
        #pragma unroll
        for (int k = 0; k < F; k++) { ssum[w][k] = sm[k]; smax[w][k] = mx[k]; }
    }
    __syncthreads();

    if (threadIdx.x == 0) {
        float fs[F], fm[F];
        #pragma unroll
        for (int k = 0; k < F; k++) { fs[k] = 0.0f; fm[k] = 0.0f; }
        for (int ww = 0; ww < 8; ww++)
            for (int k = 0; k < F; k++) {
                fs[k] += ssum[ww][k];
                fm[k] = fmaxf(fm[k], smax[ww][k]);
            }
        float cnt  = (float)(hi - lo);
        float invc = 1.0f / fmaxf(cnt, 1.0f);
        #pragma unroll
        for (int c = 0; c < 2; c++) {
            float v = blin[c];
            for (int k = 0; k < F; k++) v += fm[k] * Wlin[c * 40 + k];
            for (int k = 0; k < F; k++) v += fs[k] * invc * Wlin[c * 40 + 20 + k];
            out[g * 2 + c] = v;
        }
    }
}

// ---------------- launch ------------------------------------------------------
extern "C" void kernel_launch(void* const* d_in, const int* in_sizes, int n_in,
                              void* d_out, int out_size) {
    (void)in_sizes; (void)n_in; (void)out_size;

    const float* x      = (const float*)d_in[0];
    const int*   ei     = (const int*)  d_in[1];   // [2, NE]: row0=src, row1=dst
    const int*   batch  = (const int*)  d_in[2];
    const float* ew     = (const float*)d_in[3];
    const float* W1_rel = (const float*)d_in[4];
    const float* b1_rel = (const float*)d_in[5];
    const float* W1_root= (const float*)d_in[6];
    const float* W2_rel = (const float*)d_in[7];
    const float* b2_rel = (const float*)d_in[8];
    const float* W2_root= (const float*)d_in[9];
    const float* W3_rel = (const float*)d_in[10];
    const float* b3_rel = (const float*)d_in[11];
    const float* W3_root= (const float*)d_in[12];
    const float* W_lin  = (const float*)d_in[13];
    const float* b_lin  = (const float*)d_in[14];
    float* out = (float*)d_out;

    const int* src = ei;
    const int* dst = ei + NE;

    const int TB = 256;
    const int GB_T  = ((NN / 16) * 32 + TB - 1) / TB;   // 782 (warp per 16 nodes)
    const int GB_E8 = (NE / 8 + TB - 1) / TB;           // 1563 (guarded in-kernel)
    const int GB_W  = ((NN / 2) * 32 + TB - 1) / TB;    // 6250

    scatter_kernel<<<GB_E8, TB>>>(src, dst, ew);                          // 0

    transform_kernel<10><<<GB_T, TB>>>(x, W1_rel, b1_rel, W1_root, -1);   // 1 (+padzero)
    gather_kernel<<<GB_W, TB>>>();                                         // 2
    transform_kernel<20><<<GB_T, TB>>>(x, W2_rel, b2_rel, W2_root, 0);    // 3
    gather_kernel<<<GB_W, TB>>>();                                         // 4
    transform_kernel<20><<<GB_T, TB>>>(x, W3_rel, b3_rel, W3_root, 0);    // 5
    gather_kernel<<<GB_W, TB>>>();                                         // 6

    pool_kernel<<<NG, 256>>>(batch, W_lin, b_lin, out);                    // 7
}

// round 15
// speedup vs baseline: 1.2248x; 1.0167x over previous
#include <cuda_runtime.h>
#include <cuda_bf16.h>
#include <math.h>

#define NN 100000
#define NE 3200000
#define NG 512
#define F 20          // hidden width
#define ZP 32         // padded z row (floats) = 128B
#define CAP 96        // fixed slots per node (max degree ~65 for Poisson(32))

// ---------------- scratch (device globals; no allocation allowed) ------------
__device__ int                g_pos[NN];           // scatter cursor (starts 0, reset each call)
__device__ int                g_cnt[NN];           // padded degree (multiple of 3)
__device__ unsigned long long g_epack[(long)NN * CAP]; // bucket payload: (ew_bits<<32)|src
__device__ float              g_z[NN * ZP];        // rel-transformed, 128B-aligned rows
__device__ float              g_r[NN * F];         // root term + bias
__device__ float              g_h[NN * F];         // current node features

// ---------------- scatter: 8 edges per thread (guarded), bucketed by dst ------
__global__ void __launch_bounds__(256) scatter_kernel(const int* __restrict__ src,
                                                      const int* __restrict__ dst,
                                                      const float* __restrict__ ew) {
    int t = blockIdx.x * blockDim.x + threadIdx.x;
    if (t * 8 >= NE) return;                        // exact bound: no phantom edges
    int4   sv0 = *reinterpret_cast<const int4*>(src + t * 8);
    int4   sv1 = *reinterpret_cast<const int4*>(src + t * 8 + 4);
    int4   dv0 = *reinterpret_cast<const int4*>(dst + t * 8);
    int4   dv1 = *reinterpret_cast<const int4*>(dst + t * 8 + 4);
    float4 wv0 = *reinterpret_cast<const float4*>(ew + t * 8);
    float4 wv1 = *reinterpret_cast<const float4*>(ew + t * 8 + 4);

    int c0 = atomicAdd(&g_pos[dv0.x], 1);
    int c1 = atomicAdd(&g_pos[dv0.y], 1);
    int c2 = atomicAdd(&g_pos[dv0.z], 1);
    int c3 = atomicAdd(&g_pos[dv0.w], 1);
    int c4 = atomicAdd(&g_pos[dv1.x], 1);
    int c5 = atomicAdd(&g_pos[dv1.y], 1);
    int c6 = atomicAdd(&g_pos[dv1.z], 1);
    int c7 = atomicAdd(&g_pos[dv1.w], 1);

    if (c0 < CAP) g_epack[(long)dv0.x * CAP + c0] =
        ((unsigned long long)__float_as_uint(wv0.x) << 32) | (unsigned)sv0.x;
    if (c1 < CAP) g_epack[(long)dv0.y * CAP + c1] =
        ((unsigned long long)__float_as_uint(wv0.y) << 32) | (unsigned)sv0.y;
    if (c2 < CAP) g_epack[(long)dv0.z * CAP + c2] =
        ((unsigned long long)__float_as_uint(wv0.z) << 32) | (unsigned)sv0.z;
    if (c3 < CAP) g_epack[(long)dv0.w * CAP + c3] =
        ((unsigned long long)__float_as_uint(wv0.w) << 32) | (unsigned)sv0.w;
    if (c4 < CAP) g_epack[(long)dv1.x * CAP + c4] =
        ((unsigned long long)__float_as_uint(wv1.x) << 32) | (unsigned)sv1.x;
    if (c5 < CAP) g_epack[(long)dv1.y * CAP + c5] =
        ((unsigned long long)__float_as_uint(wv1.y) << 32) | (unsigned)sv1.y;
    if (c6 < CAP) g_epack[(long)dv1.z * CAP + c6] =
        ((unsigned long long)__float_as_uint(wv1.z) << 32) | (unsigned)sv1.z;
    if (c7 < CAP) g_epack[(long)dv1.w * CAP + c7] =
        ((unsigned long long)__float_as_uint(wv1.w) << 32) | (unsigned)sv1.w;
}

// ---------------- transform v4: warp-uniform role split -----------------------
// Block of 256 handles 128 nodes. tid<128: z[20] for node b*128+tid (role Z);
// tid>=128: r[20] for node b*128+tid-128 (role R). All lanes of a warp iterate
// the same weight element -> conflict-free LDS broadcast. FIN==10 (layer 1):
// role-Z threads additionally run padzero (pad counts to multiple of 3).
template <int FIN>
__global__ void __launch_bounds__(256) transform_kernel(const float* __restrict__ xext,
                                                        const float* __restrict__ Wrel,
                                                        const float* __restrict__ brel,
                                                        const float* __restrict__ Wroot,
                                                        int insel) {
    __shared__ float sWrel[F * FIN];
    __shared__ float sWroot[F * FIN];
    __shared__ float sb[F];
    for (int i = threadIdx.x; i < F * FIN; i += blockDim.x) {
        sWrel[i]  = Wrel[i];
        sWroot[i] = Wroot[i];
    }
    if (threadIdx.x < F) sb[threadIdx.x] = brel[threadIdx.x];
    __syncthreads();

    int tid   = threadIdx.x;
    bool is_z = tid < 128;
    int  n    = blockIdx.x * 128 + (tid & 127);
    if (n >= NN) return;

    if (FIN == 10 && is_z) {   // layer 1: finalize CSR bucket for node n
        int cnt = g_pos[n];
        if (cnt > CAP) cnt = CAP;
        int cntp = ((cnt + 2) / 3) * 3;             // multiple of 3, <= 96
        unsigned long long* pp = g_epack + (long)n * CAP;
        for (int j = cnt; j < cntp; j++) pp[j] = 0ull;
        g_cnt[n] = cntp;
        g_pos[n] = 0;
    }

    const float* fin = (insel < 0) ? xext : g_h;
    float f[FIN];
    if (FIN == 20) {
        const float4* fp = reinterpret_cast<const float4*>(fin + (long)n * FIN);
        #pragma unroll
        for (int q = 0; q < 5; q++) {
            float4 v = __ldg(fp + q);
            f[q * 4 + 0] = v.x; f[q * 4 + 1] = v.y; f[q * 4 + 2] = v.z; f[q * 4 + 3] = v.w;
        }
    } else {
        const float2* fp = reinterpret_cast<const float2*>(fin + (long)n * FIN);
        #pragma unroll
        for (int q = 0; q < 5; q++) {
            float2 v = __ldg(fp + q);
            f[q * 2 + 0] = v.x; f[q * 2 + 1] = v.y;
        }
    }

    const float* W = is_z ? sWrel : sWroot;
    float out[F];
    #pragma unroll
    for (int j = 0; j < F; j++) {
        float a = is_z ? 0.0f : sb[j];
        if (FIN == 20) {
            const float4* wr = reinterpret_cast<const float4*>(W + j * FIN);
            #pragma unroll
            for (int k = 0; k < 5; k++) {
                float4 wv = wr[k];   // broadcast LDS.128 (warp-uniform address)
                a += f[k*4+0]*wv.x + f[k*4+1]*wv.y + f[k*4+2]*wv.z + f[k*4+3]*wv.w;
            }
        } else {
            const float2* wr = reinterpret_cast<const float2*>(W + j * FIN);
            #pragma unroll
            for (int k = 0; k < 5; k++) {
                float2 wv = wr[k];   // broadcast LDS.64
                a += f[k*2+0]*wv.x + f[k*2+1]*wv.y;
            }
        }
        out[j] = a;
    }

    if (is_z) {
        float4* zp = reinterpret_cast<float4*>(g_z + (long)n * ZP);
        #pragma unroll
        for (int q = 0; q < 5; q++)
            zp[q] = make_float4(out[q*4], out[q*4+1], out[q*4+2], out[q*4+3]);
    } else {
        float4* rp = reinterpret_cast<float4*>(g_r + (long)n * F);
        #pragma unroll
        for (int q = 0; q < 5; q++)
            rp[q] = make_float4(out[q*4], out[q*4+1], out[q*4+2], out[q*4+3]);
    }
}

// ---------------- gather: 2 nodes per warp, 15 lanes each (3 edges x 5 quads) -
// (round-11 version: pad-to-3, warp-uniform break in sub loop)
__global__ void __launch_bounds__(256) gather_kernel() {
    const unsigned FULL = 0xffffffffu;
    int gwarp = (blockIdx.x * blockDim.x + threadIdx.x) >> 5;   // 0..NN/2-1
    if (gwarp >= NN / 2) return;
    int lane   = threadIdx.x & 31;
    int half   = lane & 16;         // 0 or 16
    int local  = lane & 15;         // 0..15
    int e_slot = local / 5;         // 0..2 (3 for local 15, unused)
    int q      = local % 5;
    const bool use = local < 15;

    int  node = 2 * gwarp + (half >> 4);
    long s0   = (long)node * CAP;
    int  cntp = g_cnt[node];                          // multiple of 3
    int  cmax = max(cntp, __shfl_xor_sync(FULL, cntp, 16));

    float4 acc = make_float4(0.f, 0.f, 0.f, 0.f);

    for (int base = 0; base < cmax; base += 15) {
        unsigned lo = 0u, hi = 0u;
        int idx = base + local;
        if (use && idx < cntp) {
            unsigned long long pk = g_epack[s0 + idx];
            lo = (unsigned)pk;
            hi = (unsigned)(pk >> 32);
        }
        int rem = cmax - base;       // multiple of 3, > 0
        #pragma unroll
        for (int sub = 0; sub < 5; sub++) {
            if (sub * 3 >= rem) break;               // warp-uniform
            int   sl = half + sub * 3 + e_slot;      // payload lane for this slot
            int   s  = __shfl_sync(FULL, lo, sl);
            float w  = __uint_as_float(__shfl_sync(FULL, hi, sl));
            if (use) {
                float4 row = *reinterpret_cast<const float4*>(g_z + s * ZP + q * 4);
                acc.x += w * row.x;
                acc.y += w * row.y;
                acc.z += w * row.z;
                acc.w += w * row.w;
            }
        }
    }

    // reduce 3 edge-slots within each half: locals 0-4 <- (0-4)+(5-9)+(10-14)
    float4 a1, tot;
    a1.x = acc.x + __shfl_down_sync(FULL, acc.x, 5);
    a1.y = acc.y + __shfl_down_sync(FULL, acc.y, 5);
    a1.z = acc.z + __shfl_down_sync(FULL, acc.z, 5);
    a1.w = acc.w + __shfl_down_sync(FULL, acc.w, 5);
    tot.x = a1.x + __shfl_down_sync(FULL, acc.x, 10);
    tot.y = a1.y + __shfl_down_sync(FULL, acc.y, 10);
    tot.z = a1.z + __shfl_down_sync(FULL, acc.z, 10);
    tot.w = a1.w + __shfl_down_sync(FULL, acc.w, 10);

    // locals 0-4 hold quad q=local; add root term, normalize, relu, store
    float4 val = make_float4(0.f, 0.f, 0.f, 0.f);
    if (local < 5) {
        float4 rq = *reinterpret_cast<const float4*>(g_r + (long)node * F + local * 4);
        val.x = tot.x + rq.x;
        val.y = tot.y + rq.y;
        val.z = tot.z + rq.z;
        val.w = tot.w + rq.w;
    }
    float ss = val.x * val.x + val.y * val.y + val.z * val.z + val.w * val.w;
    float sstot = ss
        + __shfl_down_sync(FULL, ss, 1)
        + __shfl_down_sync(FULL, ss, 2)
        + __shfl_down_sync(FULL, ss, 3)
        + __shfl_down_sync(FULL, ss, 4);
    sstot = __shfl_sync(FULL, sstot, half);   // each half broadcasts its total
    float inv = 1.0f / fmaxf(sqrtf(sstot), 1e-12f);

    if (local < 5) {
        float4 o;
        o.x = fmaxf(val.x * inv, 0.0f);
        o.y = fmaxf(val.y * inv, 0.0f);
        o.z = fmaxf(val.z * inv, 0.0f);
        o.w = fmaxf(val.w * inv, 0.0f);
        *reinterpret_cast<float4*>(g_h + (long)node * F + local * 4) = o;
    }
}

// ---------------- pooling + final linear (batch sorted -> no atomics) --------
__device__ __forceinline__ int lower_bound_i(const int* __restrict__ a, int n, int key) {
    int lo = 0, hi = n;
    while (lo < hi) {
        int m = (lo + hi) >> 1;
        if (a[m] < key) lo = m + 1; else hi = m;
    }
    return lo;
}

__global__ void __launch_bounds__(256) pool_kernel(const int* __restrict__ batch,
                                                   const float* __restrict__ Wlin,
                                                   const float* __restrict__ blin,
                                                   float* __restrict__ out) {
    const float* emb = g_h;
    int g = blockIdx.x;

    __shared__ int s_lo, s_hi;
    if (threadIdx.x == 0) {
        s_lo = lower_bound_i(batch, NN, g);
        s_hi = lower_bound_i(batch, NN, g + 1);
    }
    __syncthreads();
    int lo = s_lo, hi = s_hi;

    float sm[F], mx[F];
    #pragma unroll
    for (int k = 0; k < F; k++) { sm[k] = 0.0f; mx[k] = 0.0f; }

    for (int i = lo + threadIdx.x; i < hi; i += blockDim.x) {
        const float* r = emb + (long)i * F;
        #pragma unroll
        for (int k = 0; k < F; k++) {
            float v = __ldg(r + k);
            sm[k] += v;
            mx[k] = fmaxf(mx[k], v);
        }
    }

    #pragma unroll
    for (int o = 16; o > 0; o >>= 1) {
        #pragma unroll
        for (int k = 0; k < F; k++) {
            sm[k] += __shfl_down_sync(0xffffffffu, sm[k], o);
            mx[k] = fmaxf(mx[k], __shfl_down_sync(0xffffffffu, mx[k], o));
        }
    }

    __shared__ float ssum[8][F];
    __shared__ float smax[8][F];
    int w = threadIdx.x >> 5, lane = threadIdx.x & 31;
    if (lane == 0) {
        #pragma unroll
        for (int k = 0; k < F; k++) { ssum[w][k] = sm[k]; smax[w][k] = mx[k]; }
    }
    __syncthreads();

    if (threadIdx.x == 0) {
        float fs[F], fm[F];
        #pragma unroll
        for (int k = 0; k < F; k++) { fs[k] = 0.0f; fm[k] = 0.0f; }
        for (int ww = 0; ww < 8; ww++)
            for (int k = 0; k < F; k++) {
                fs[k] += ssum[ww][k];
                fm[k] = fmaxf(fm[k], smax[ww][k]);
            }
        float cnt  = (float)(hi - lo);
        float invc = 1.0f / fmaxf(cnt, 1.0f);
        #pragma unroll
        for (int c = 0; c < 2; c++) {
            float v = blin[c];
            for (int k = 0; k < F; k++) v += fm[k] * Wlin[c * 40 + k];
            for (int k = 0; k < F; k++) v += fs[k] * invc * Wlin[c * 40 + 20 + k];
            out[g * 2 + c] = v;
        }
    }
}

// ---------------- launch ------------------------------------------------------
extern "C" void kernel_launch(void* const* d_in, const int* in_sizes, int n_in,
                              void* d_out, int out_size) {
    (void)in_sizes; (void)n_in; (void)out_size;

    const float* x      = (const float*)d_in[0];
    const int*   ei     = (const int*)  d_in[1];   // [2, NE]: row0=src, row1=dst
    const int*   batch  = (const int*)  d_in[2];
    const float* ew     = (const float*)d_in[3];
    const float* W1_rel = (const float*)d_in[4];
    const float* b1_rel = (const float*)d_in[5];
    const float* W1_root= (const float*)d_in[6];
    const float* W2_rel = (const float*)d_in[7];
    const float* b2_rel = (const float*)d_in[8];
    const float* W2_root= (const float*)d_in[9];
    const float* W3_rel = (const float*)d_in[10];
    const float* b3_rel = (const float*)d_in[11];
    const float* W3_root= (const float*)d_in[12];
    const float* W_lin  = (const float*)d_in[13];
    const float* b_lin  = (const float*)d_in[14];
    float* out = (float*)d_out;

    const int* src = ei;
    const int* dst = ei + NE;

    const int TB = 256;
    const int GB_T  = (NN + 127) / 128;                 // 782 (128 nodes per block)
    const int GB_E8 = (NE / 8 + TB - 1) / TB;           // 1563 (guarded in-kernel)
    const int GB_W  = ((NN / 2) * 32 + TB - 1) / TB;    // 6250

    scatter_kernel<<<GB_E8, TB>>>(src, dst, ew);                          // 0

    transform_kernel<10><<<GB_T, TB>>>(x, W1_rel, b1_rel, W1_root, -1);   // 1 (+padzero)
    gather_kernel<<<GB_W, TB>>>();                                         // 2
    transform_kernel<20><<<GB_T, TB>>>(x, W2_rel, b2_rel, W2_root, 0);    // 3
    gather_kernel<<<GB_W, TB>>>();                                         // 4
    transform_kernel<20><<<GB_T, TB>>>(x, W3_rel, b3_rel, W3_root, 0);    // 5
    gather_kernel<<<GB_W, TB>>>();                                         // 6

    pool_kernel<<<NG, 256>>>(batch, W_lin, b_lin, out);                    // 7
}

// round 16
// speedup vs baseline: 1.3796x; 1.1264x over previous
#include <cuda_runtime.h>
#include <cuda_bf16.h>
#include <math.h>

#define NN 100000
#define NE 3200000
#define NG 512
#define F 20          // hidden width
#define ZP 32         // padded z row (floats) = 128B
#define CAP 96        // fixed slots per node (max degree ~65 for Poisson(32))

// ---------------- scratch (device globals; no allocation allowed) ------------
__device__ int                g_pos[NN];           // scatter cursor (starts 0, reset each call)
__device__ int                g_cnt[NN];           // padded degree (multiple of 3)
__device__ unsigned long long g_epack[(long)NN * CAP]; // bucket payload: (ew_bits<<32)|src
__device__ float              g_z[NN * ZP];        // rel-transformed, 128B-aligned rows
__device__ float              g_r[NN * F];         // root term + bias
__device__ float              g_h[NN * F];         // current node features

// ---------------- scatter: 8 edges per thread (guarded), bucketed by dst ------
__global__ void __launch_bounds__(256) scatter_kernel(const int* __restrict__ src,
                                                      const int* __restrict__ dst,
                                                      const float* __restrict__ ew) {
    int t = blockIdx.x * blockDim.x + threadIdx.x;
    if (t * 8 >= NE) return;                        // exact bound: no phantom edges
    int4   sv0 = *reinterpret_cast<const int4*>(src + t * 8);
    int4   sv1 = *reinterpret_cast<const int4*>(src + t * 8 + 4);
    int4   dv0 = *reinterpret_cast<const int4*>(dst + t * 8);
    int4   dv1 = *reinterpret_cast<const int4*>(dst + t * 8 + 4);
    float4 wv0 = *reinterpret_cast<const float4*>(ew + t * 8);
    float4 wv1 = *reinterpret_cast<const float4*>(ew + t * 8 + 4);

    int c0 = atomicAdd(&g_pos[dv0.x], 1);
    int c1 = atomicAdd(&g_pos[dv0.y], 1);
    int c2 = atomicAdd(&g_pos[dv0.z], 1);
    int c3 = atomicAdd(&g_pos[dv0.w], 1);
    int c4 = atomicAdd(&g_pos[dv1.x], 1);
    int c5 = atomicAdd(&g_pos[dv1.y], 1);
    int c6 = atomicAdd(&g_pos[dv1.z], 1);
    int c7 = atomicAdd(&g_pos[dv1.w], 1);

    if (c0 < CAP) g_epack[(long)dv0.x * CAP + c0] =
        ((unsigned long long)__float_as_uint(wv0.x) << 32) | (unsigned)sv0.x;
    if (c1 < CAP) g_epack[(long)dv0.y * CAP + c1] =
        ((unsigned long long)__float_as_uint(wv0.y) << 32) | (unsigned)sv0.y;
    if (c2 < CAP) g_epack[(long)dv0.z * CAP + c2] =
        ((unsigned long long)__float_as_uint(wv0.z) << 32) | (unsigned)sv0.z;
    if (c3 < CAP) g_epack[(long)dv0.w * CAP + c3] =
        ((unsigned long long)__float_as_uint(wv0.w) << 32) | (unsigned)sv0.w;
    if (c4 < CAP) g_epack[(long)dv1.x * CAP + c4] =
        ((unsigned long long)__float_as_uint(wv1.x) << 32) | (unsigned)sv1.x;
    if (c5 < CAP) g_epack[(long)dv1.y * CAP + c5] =
        ((unsigned long long)__float_as_uint(wv1.y) << 32) | (unsigned)sv1.y;
    if (c6 < CAP) g_epack[(long)dv1.z * CAP + c6] =
        ((unsigned long long)__float_as_uint(wv1.z) << 32) | (unsigned)sv1.z;
    if (c7 < CAP) g_epack[(long)dv1.w * CAP + c7] =
        ((unsigned long long)__float_as_uint(wv1.w) << 32) | (unsigned)sv1.w;
}

// ---------------- padzero: finalize counts (pad to 3), zero pads, reset cursor
__global__ void __launch_bounds__(256) padzero_kernel() {
    int n = blockIdx.x * blockDim.x + threadIdx.x;
    if (n >= NN) return;
    int cnt = g_pos[n];
    if (cnt > CAP) cnt = CAP;
    int cntp = ((cnt + 2) / 3) * 3;                 // multiple of 3, <= 96
    unsigned long long* p = g_epack + (long)n * CAP;
    for (int j = cnt; j < cntp; j++) p[j] = 0ull;   // w=0, src=0 -> harmless
    g_cnt[n] = cntp;
    g_pos[n] = 0;    // restore invariant for next launch
}

// ---------------- transform v1-streamed: thread per node, quad-streamed stores
// Scalar warp-uniform smem broadcasts (proven fastest); outputs stored quad-by-
// quad so live regs ~45 instead of 128.
template <int FIN>
__global__ void __launch_bounds__(256) transform_kernel(const float* __restrict__ xext,
                                                        const float* __restrict__ Wrel,
                                                        const float* __restrict__ brel,
                                                        const float* __restrict__ Wroot,
                                                        int insel) {
    __shared__ float sWrel[F * FIN];
    __shared__ float sWroot[F * FIN];
    __shared__ float sb[F];
    for (int i = threadIdx.x; i < F * FIN; i += blockDim.x) {
        sWrel[i]  = Wrel[i];
        sWroot[i] = Wroot[i];
    }
    if (threadIdx.x < F) sb[threadIdx.x] = brel[threadIdx.x];
    __syncthreads();

    const float* fin = (insel < 0) ? xext : g_h;
    int n = blockIdx.x * blockDim.x + threadIdx.x;
    if (n >= NN) return;

    float f[FIN];
    if (FIN == 20) {
        const float4* p = reinterpret_cast<const float4*>(fin + (long)n * FIN);
        #pragma unroll
        for (int q = 0; q < 5; q++) {
            float4 v = p[q];
            f[q * 4 + 0] = v.x; f[q * 4 + 1] = v.y; f[q * 4 + 2] = v.z; f[q * 4 + 3] = v.w;
        }
    } else {  // FIN == 10
        const float2* p = reinterpret_cast<const float2*>(fin + (long)n * FIN);
        #pragma unroll
        for (int q = 0; q < 5; q++) {
            float2 v = p[q];
            f[q * 2 + 0] = v.x; f[q * 2 + 1] = v.y;
        }
    }

    float4* zp = reinterpret_cast<float4*>(g_z + (long)n * ZP);
    float4* rp = reinterpret_cast<float4*>(g_r + (long)n * F);

    #pragma unroll
    for (int jq = 0; jq < 5; jq++) {
        float zq[4], rq[4];
        #pragma unroll
        for (int i = 0; i < 4; i++) {
            int j = jq * 4 + i;
            float za = 0.0f, ra = sb[j];
            #pragma unroll
            for (int k = 0; k < FIN; k++) {
                za += f[k] * sWrel[j * FIN + k];
                ra += f[k] * sWroot[j * FIN + k];
            }
            zq[i] = za; rq[i] = ra;
        }
        zp[jq] = make_float4(zq[0], zq[1], zq[2], zq[3]);
        rp[jq] = make_float4(rq[0], rq[1], rq[2], rq[3]);
    }
}

// ---------------- gather: 2 nodes per warp, 15 lanes each (3 edges x 5 quads) -
// (round-11 version: pad-to-3, warp-uniform break in sub loop)
__global__ void __launch_bounds__(256) gather_kernel() {
    const unsigned FULL = 0xffffffffu;
    int gwarp = (blockIdx.x * blockDim.x + threadIdx.x) >> 5;   // 0..NN/2-1
    if (gwarp >= NN / 2) return;
    int lane   = threadIdx.x & 31;
    int half   = lane & 16;         // 0 or 16
    int local  = lane & 15;         // 0..15
    int e_slot = local / 5;         // 0..2 (3 for local 15, unused)
    int q      = local % 5;
    const bool use = local < 15;

    int  node = 2 * gwarp + (half >> 4);
    long s0   = (long)node * CAP;
    int  cntp = g_cnt[node];                          // multiple of 3
    int  cmax = max(cntp, __shfl_xor_sync(FULL, cntp, 16));

    float4 acc = make_float4(0.f, 0.f, 0.f, 0.f);

    for (int base = 0; base < cmax; base += 15) {
        unsigned lo = 0u, hi = 0u;
        int idx = base + local;
        if (use && idx < cntp) {
            unsigned long long pk = g_epack[s0 + idx];
            lo = (unsigned)pk;
            hi = (unsigned)(pk >> 32);
        }
        int rem = cmax - base;       // multiple of 3, > 0
        #pragma unroll
        for (int sub = 0; sub < 5; sub++) {
            if (sub * 3 >= rem) break;               // warp-uniform
            int   sl = half + sub * 3 + e_slot;      // payload lane for this slot
            int   s  = __shfl_sync(FULL, lo, sl);
            float w  = __uint_as_float(__shfl_sync(FULL, hi, sl));
            if (use) {
                float4 row = *reinterpret_cast<const float4*>(g_z + s * ZP + q * 4);
                acc.x += w * row.x;
                acc.y += w * row.y;
                acc.z += w * row.z;
                acc.w += w * row.w;
            }
        }
    }

    // reduce 3 edge-slots within each half: locals 0-4 <- (0-4)+(5-9)+(10-14)
    float4 a1, tot;
    a1.x = acc.x + __shfl_down_sync(FULL, acc.x, 5);
    a1.y = acc.y + __shfl_down_sync(FULL, acc.y, 5);
    a1.z = acc.z + __shfl_down_sync(FULL, acc.z, 5);
    a1.w = acc.w + __shfl_down_sync(FULL, acc.w, 5);
    tot.x = a1.x + __shfl_down_sync(FULL, acc.x, 10);
    tot.y = a1.y + __shfl_down_sync(FULL, acc.y, 10);
    tot.z = a1.z + __shfl_down_sync(FULL, acc.z, 10);
    tot.w = a1.w + __shfl_down_sync(FULL, acc.w, 10);

    // locals 0-4 hold quad q=local; add root term, normalize, relu, store
    float4 val = make_float4(0.f, 0.f, 0.f, 0.f);
    if (local < 5) {
        float4 rq = *reinterpret_cast<const float4*>(g_r + (long)node * F + local * 4);
        val.x = tot.x + rq.x;
        val.y = tot.y + rq.y;
        val.z = tot.z + rq.z;
        val.w = tot.w + rq.w;
    }
    float ss = val.x * val.x + val.y * val.y + val.z * val.z + val.w * val.w;
    float sstot = ss
        + __shfl_down_sync(FULL, ss, 1)
        + __shfl_down_sync(FULL, ss, 2)
        + __shfl_down_sync(FULL, ss, 3)
        + __shfl_down_sync(FULL, ss, 4);
    sstot = __shfl_sync(FULL, sstot, half);   // each half broadcasts its total
    float inv = 1.0f / fmaxf(sqrtf(sstot), 1e-12f);

    if (local < 5) {
        float4 o;
        o.x = fmaxf(val.x * inv, 0.0f);
        o.y = fmaxf(val.y * inv, 0.0f);
        o.z = fmaxf(val.z * inv, 0.0f);
        o.w = fmaxf(val.w * inv, 0.0f);
        *reinterpret_cast<float4*>(g_h + (long)node * F + local * 4) = o;
    }
}

// ---------------- pooling + final linear (batch sorted -> no atomics) --------
__device__ __forceinline__ int lower_bound_i(const int* __restrict__ a, int n, int key) {
    int lo = 0, hi = n;
    while (lo < hi) {
        int m = (lo + hi) >> 1;
        if (a[m] < key) lo = m + 1; else hi = m;
    }
    return lo;
}

__global__ void __launch_bounds__(256) pool_kernel(const int* __restrict__ batch,
                                                   const float* __restrict__ Wlin,
                                                   const float* __restrict__ blin,
                                                   float* __restrict__ out) {
    const float* emb = g_h;
    int g = blockIdx.x;

    __shared__ int s_lo, s_hi;
    if (threadIdx.x == 0) {
        s_lo = lower_bound_i(batch, NN, g);
        s_hi = lower_bound_i(batch, NN, g + 1);
    }
    __syncthreads();
    int lo = s_lo, hi = s_hi;

    float sm[F], mx[F];
    #pragma unroll
    for (int k = 0; k < F; k++) { sm[k] = 0.0f; mx[k] = 0.0f; }

    for (int i = lo + threadIdx.x; i < hi; i += blockDim.x) {
        const float* r = emb + (long)i * F;
        #pragma unroll
        for (int k = 0; k < F; k++) {
            float v = __ldg(r + k);
            sm[k] += v;
            mx[k] = fmaxf(mx[k], v);
        }
    }

    #pragma unroll
    for (int o = 16; o > 0; o >>= 1) {
        #pragma unroll
        for (int k = 0; k < F; k++) {
            sm[k] += __shfl_down_sync(0xffffffffu, sm[k], o);
            mx[k] = fmaxf(mx[k], __shfl_down_sync(0xffffffffu, mx[k], o));
        }
    }

    __shared__ float ssum[8][F];
    __shared__ float smax[8][F];
    int w = threadIdx.x >> 5, lane = threadIdx.x & 31;
    if (lane == 0) {
        #pragma unroll
        for (int k = 0; k < F; k++) { ssum[w][k] = sm[k]; smax[w][k] = mx[k]; }
    }
    __syncthreads();

    if (threadIdx.x == 0) {
        float fs[F], fm[F];
        #pragma unroll
        for (int k = 0; k < F; k++) { fs[k] = 0.0f; fm[k] = 0.0f; }
        for (int ww = 0; ww < 8; ww++)
            for (int k = 0; k < F; k++) {
                fs[k] += ssum[ww][k];
                fm[k] = fmaxf(fm[k], smax[ww][k]);
            }
        float cnt  = (float)(hi - lo);
        float invc = 1.0f / fmaxf(cnt, 1.0f);
        #pragma unroll
        for (int c = 0; c < 2; c++) {
            float v = blin[c];
            for (int k = 0; k < F; k++) v += fm[k] * Wlin[c * 40 + k];
            for (int k = 0; k < F; k++) v += fs[k] * invc * Wlin[c * 40 + 20 + k];
            out[g * 2 + c] = v;
        }
    }
}

// ---------------- launch ------------------------------------------------------
extern "C" void kernel_launch(void* const* d_in, const int* in_sizes, int n_in,
                              void* d_out, int out_size) {
    (void)in_sizes; (void)n_in; (void)out_size;

    const float* x      = (const float*)d_in[0];
    const int*   ei     = (const int*)  d_in[1];   // [2, NE]: row0=src, row1=dst
    const int*   batch  = (const int*)  d_in[2];
    const float* ew     = (const float*)d_in[3];
    const float* W1_rel = (const float*)d_in[4];
    const float* b1_rel = (const float*)d_in[5];
    const float* W1_root= (const float*)d_in[6];
    const float* W2_rel = (const float*)d_in[7];
    const float* b2_rel = (const float*)d_in[8];
    const float* W2_root= (const float*)d_in[9];
    const float* W3_rel = (const float*)d_in[10];
    const float* b3_rel = (const float*)d_in[11];
    const float* W3_root= (const float*)d_in[12];
    const float* W_lin  = (const float*)d_in[13];
    const float* b_lin  = (const float*)d_in[14];
    float* out = (float*)d_out;

    const int* src = ei;
    const int* dst = ei + NE;

    const int TB = 256;
    const int GB_N  = (NN + TB - 1) / TB;               // 391
    const int GB_E8 = (NE / 8 + TB - 1) / TB;           // 1563 (guarded in-kernel)
    const int GB_W  = ((NN / 2) * 32 + TB - 1) / TB;    // 6250

    // fork: scatter runs concurrently with transform-1 (independent work)
    cudaStream_t s2;
    cudaStreamCreateWithFlags(&s2, cudaStreamNonBlocking);
    cudaEvent_t ev_fork, ev_join;
    cudaEventCreateWithFlags(&ev_fork, cudaEventDisableTiming);
    cudaEventCreateWithFlags(&ev_join, cudaEventDisableTiming);

    cudaEventRecord(ev_fork, 0);
    cudaStreamWaitEvent(s2, ev_fork, 0);
    scatter_kernel<<<GB_E8, TB, 0, s2>>>(src, dst, ew);
    cudaEventRecord(ev_join, s2);

    transform_kernel<10><<<GB_N, TB>>>(x, W1_rel, b1_rel, W1_root, -1);  // overlapped

    cudaStreamWaitEvent(0, ev_join, 0);   // join: padzero needs scatter cursors
    padzero_kernel<<<GB_N, TB>>>();

    gather_kernel<<<GB_W, TB>>>();
    transform_kernel<20><<<GB_N, TB>>>(x, W2_rel, b2_rel, W2_root, 0);
    gather_kernel<<<GB_W, TB>>>();
    transform_kernel<20><<<GB_N, TB>>>(x, W3_rel, b3_rel, W3_root, 0);
    gather_kernel<<<GB_W, TB>>>();

    pool_kernel<<<NG, 256>>>(batch, W_lin, b_lin, out);

    cudaEventDestroy(ev_fork);
    cudaEventDestroy(ev_join);
    cudaStreamDestroy(s2);
}